// round 1
// baseline (speedup 1.0000x reference)
#include <cuda_runtime.h>
#include <math.h>

#define BB 8
#define LL 2048
#define DM 512
#define DI 1024
#define NH 16
#define HD 64
#define NS 16
#define CD 1056
#define DIP 2096
#define MT (BB*LL)   // 16384 tokens

// ---------------- scratch (static device globals; no allocation) ----------------
__device__ float g_zx [2ull*MT*DIP];   // in_proj output, both dirs   (~275 MB)
__device__ float g_xbc[2ull*MT*CD];    // conv+silu output            (~138 MB)
__device__ float g_dt [2ull*MT*NH];
__device__ float g_dA [2ull*MT*NH];
__device__ float g_y  [2ull*MT*DI];    // scan output (incl. Dp*x)    (~134 MB)
__device__ float g_g  [2ull*MT*DI];    // gated-norm output           (~134 MB)

__device__ __forceinline__ float siluf(float v)     { return v / (1.f + expf(-v)); }
__device__ __forceinline__ float softplusf(float v) { return fmaxf(v, 0.f) + log1pf(expf(-fabsf(v))); }

// ---------------- GEMM: C[M,N] = A[M,K] * B[N,K]^T  (M = grid.y*128, multiple of 128) ----
template<bool ACC>
__global__ __launch_bounds__(256)
void gemm_tn(const float* __restrict__ A, const float* __restrict__ B,
             float* __restrict__ C, int N, int K, int ldc)
{
    __shared__ float As[16][132];
    __shared__ float Bs[16][132];
    const int tid = threadIdx.x;
    const int m0 = blockIdx.y * 128;
    const int n0 = blockIdx.x * 128;
    const int tx = tid & 15, ty = tid >> 4;
    const int lr = tid >> 2;          // 0..63
    const int lc = (tid & 3) << 2;    // 0,4,8,12

    float acc[8][8];
#pragma unroll
    for (int i = 0; i < 8; i++)
#pragma unroll
        for (int j = 0; j < 8; j++) acc[i][j] = 0.f;

    for (int k0 = 0; k0 < K; k0 += 16) {
#pragma unroll
        for (int i = 0; i < 2; ++i) {
            int row = lr + i * 64;
            float4 v = *(const float4*)(A + (size_t)(m0 + row) * K + k0 + lc);
            As[lc+0][row] = v.x; As[lc+1][row] = v.y; As[lc+2][row] = v.z; As[lc+3][row] = v.w;
        }
#pragma unroll
        for (int i = 0; i < 2; ++i) {
            int row = lr + i * 64;
            float4 v = make_float4(0.f, 0.f, 0.f, 0.f);
            if (n0 + row < N)
                v = *(const float4*)(B + (size_t)(n0 + row) * K + k0 + lc);
            Bs[lc+0][row] = v.x; Bs[lc+1][row] = v.y; Bs[lc+2][row] = v.z; Bs[lc+3][row] = v.w;
        }
        __syncthreads();
#pragma unroll
        for (int k = 0; k < 16; ++k) {
            float ra[8], rb[8];
#pragma unroll
            for (int i = 0; i < 8; i++) { ra[i] = As[k][ty*8 + i]; rb[i] = Bs[k][tx*8 + i]; }
#pragma unroll
            for (int i = 0; i < 8; i++)
#pragma unroll
                for (int j = 0; j < 8; j++) acc[i][j] = fmaf(ra[i], rb[j], acc[i][j]);
        }
        __syncthreads();
    }

#pragma unroll
    for (int i = 0; i < 8; i++) {
        int m = m0 + ty*8 + i;
#pragma unroll
        for (int j = 0; j < 8; j++) {
            int n = n0 + tx*8 + j;
            if (n < N) {
                size_t o = (size_t)m * ldc + n;
                if (ACC) C[o] += acc[i][j]; else C[o] = acc[i][j];
            }
        }
    }
}

// ---------------- depthwise causal/anticausal conv(4) + bias + SiLU ----------------
__global__ __launch_bounds__(256)
void conv_silu_k(const float* __restrict__ cwF, const float* __restrict__ cbF,
                 const float* __restrict__ cwB, const float* __restrict__ cbB)
{
    long idx = (long)blockIdx.x * 256 + threadIdx.x;
    const long total = 2L * MT * CD;
    if (idx >= total) return;
    int  c = (int)(idx % CD);
    long r = idx / CD;                 // d*MT + b*LL + t
    int  t = (int)(r % LL);
    int  d = (int)(r / MT);

    const float* w = (d == 0 ? cwF : cwB) + c * 4;
    float acc = (d == 0 ? cbF : cbB)[c];
    const float* zin = g_zx + r * (long)DIP + DI + c;   // xBC region of zxbcdt

    if (d == 0) {
#pragma unroll
        for (int k = 0; k < 4; k++) {
            int tt = t - 3 + k;
            if (tt >= 0) acc = fmaf(w[k], zin[(long)(k - 3) * DIP], acc);
        }
    } else {
#pragma unroll
        for (int k = 0; k < 4; k++) {
            int tt = t + 3 - k;
            if (tt < LL) acc = fmaf(w[k], zin[(long)(3 - k) * DIP], acc);
        }
    }
    g_xbc[idx] = siluf(acc);
}

// ---------------- dt = softplus(dt_raw + bias); dA = exp(dt * -exp(A_log)) ----------------
__global__ __launch_bounds__(256)
void dadt_k(const float* __restrict__ dbF, const float* __restrict__ alF,
            const float* __restrict__ dbB, const float* __restrict__ alB)
{
    long idx = (long)blockIdx.x * 256 + threadIdx.x;
    if (idx >= 2L * MT * NH) return;
    int  h = (int)(idx % NH);
    long r = idx / NH;
    int  d = (int)(r / MT);
    float draw = g_zx[r * (long)DIP + DI + CD + h];
    float dt = softplusf(draw + (d == 0 ? dbF : dbB)[h]);
    float A  = -expf((d == 0 ? alF : alB)[h]);
    g_dt[idx] = dt;
    g_dA[idx] = expf(dt * A);
}

// ---------------- selective scan: one block per (d,b,h); 64 threads = headdim ----------------
__global__ __launch_bounds__(64)
void scan_k(const float* __restrict__ DpF, const float* __restrict__ DpB)
{
    int bid = blockIdx.x;          // 256
    int d   = bid >> 7;
    int rem = bid & 127;
    int b   = rem >> 4;
    int h   = rem & 15;
    int p   = threadIdx.x;         // 0..63

    __shared__ float sBC[32];      // B[0..15], C[0..15]
    float hs[16];
#pragma unroll
    for (int n = 0; n < 16; n++) hs[n] = 0.f;
    float dp = (d == 0 ? DpF : DpB)[h];

    long base0 = (long)d * MT + (long)b * LL;
    int  t0 = (d == 0) ? 0 : LL - 1;
    int  st = (d == 0) ? 1 : -1;

    for (int s = 0; s < LL; ++s) {
        int  t   = t0 + s * st;
        long row = base0 + t;
        if (p < 32) sBC[p] = g_xbc[row * (long)CD + DI + p];
        __syncthreads();

        float xv  = g_xbc[row * (long)CD + h * HD + p];
        float dtv = g_dt[row * (long)NH + h];
        float dAv = g_dA[row * (long)NH + h];
        float coef = dtv * xv;
        float y = 0.f;
#pragma unroll
        for (int n = 0; n < 16; n++) {
            hs[n] = fmaf(hs[n], dAv, coef * sBC[n]);
            y = fmaf(hs[n], sBC[16 + n], y);
        }
        g_y[row * (long)DI + h * HD + p] = fmaf(dp, xv, y);
        __syncthreads();
    }
}

// ---------------- gated RMSNorm: g = (y*silu(z)) * rsqrt(mean(v^2)+eps) * norm_w ----------------
__global__ __launch_bounds__(256)
void gnorm_k(const float* __restrict__ nwF, const float* __restrict__ nwB)
{
    long r = blockIdx.x;                       // 0 .. 2*MT-1
    int  d = (int)(r / MT);
    const float* nw = (d == 0) ? nwF : nwB;
    const float* yp = g_y  + r * (long)DI;
    const float* zp = g_zx + r * (long)DIP;    // z = first DI entries

    int i0 = threadIdx.x * 4;
    float v[4];
    float ss = 0.f;
#pragma unroll
    for (int j = 0; j < 4; j++) {
        float val = yp[i0 + j] * siluf(zp[i0 + j]);
        v[j] = val;
        ss = fmaf(val, val, ss);
    }
#pragma unroll
    for (int off = 16; off; off >>= 1) ss += __shfl_xor_sync(~0u, ss, off);
    __shared__ float ws[8];
    if ((threadIdx.x & 31) == 0) ws[threadIdx.x >> 5] = ss;
    __syncthreads();
    float tot = ws[0] + ws[1] + ws[2] + ws[3] + ws[4] + ws[5] + ws[6] + ws[7];
    float scale = rsqrtf(tot * (1.f / 1024.f) + 1e-5f);
#pragma unroll
    for (int j = 0; j < 4; j++)
        g_g[r * (long)DI + i0 + j] = v[j] * scale * nw[i0 + j];
}

// ---------------- launch ----------------
extern "C" void kernel_launch(void* const* d_in, const int* in_sizes, int n_in,
                              void* d_out, int out_size)
{
    const float* x   = (const float*)d_in[0];
    const float* ipwF = (const float*)d_in[1];
    const float* cwF  = (const float*)d_in[2];
    const float* cbF  = (const float*)d_in[3];
    const float* dbF  = (const float*)d_in[4];
    const float* alF  = (const float*)d_in[5];
    const float* dpF  = (const float*)d_in[6];
    const float* nwF  = (const float*)d_in[7];
    const float* opF  = (const float*)d_in[8];
    const float* ipwB = (const float*)d_in[9];
    const float* cwB  = (const float*)d_in[10];
    const float* cbB  = (const float*)d_in[11];
    const float* dbB  = (const float*)d_in[12];
    const float* alB  = (const float*)d_in[13];
    const float* dpB  = (const float*)d_in[14];
    const float* nwB  = (const float*)d_in[15];
    const float* opB  = (const float*)d_in[16];
    float* out = (float*)d_out;

    float *zx_d, *g_d;
    cudaGetSymbolAddress((void**)&zx_d, g_zx);
    cudaGetSymbolAddress((void**)&g_d,  g_g);

    // 1) in_proj for both directions (same A = x; pointwise, so direction-independent)
    gemm_tn<false><<<dim3(17, 128), 256>>>(x, ipwF, zx_d,                 DIP, DM, DIP);
    gemm_tn<false><<<dim3(17, 128), 256>>>(x, ipwB, zx_d + (size_t)MT*DIP, DIP, DM, DIP);

    // 2) depthwise conv + silu (causal fwd, anticausal bwd)
    {
        long total = 2L * MT * CD;
        conv_silu_k<<<(unsigned)((total + 255) / 256), 256>>>(cwF, cbF, cwB, cbB);
    }

    // 3) dt / dA precompute
    dadt_k<<<(2 * MT * NH) / 256, 256>>>(dbF, alF, dbB, alB);

    // 4) selective scan (fwd left->right, bwd right->left)
    scan_k<<<256, 64>>>(dpF, dpB);

    // 5) gated RMSNorm
    gnorm_k<<<2 * MT, 256>>>(nwF, nwB);

    // 6) out_proj: fwd writes, bwd accumulates => out = fwd + bwd
    gemm_tn<false><<<dim3(4, 128), 256>>>(g_d,                   opF, out, DM, DI, DM);
    gemm_tn<true ><<<dim3(4, 128), 256>>>(g_d + (size_t)MT * DI, opB, out, DM, DI, DM);
}

// round 3
// speedup vs baseline: 1.8320x; 1.8320x over previous
#include <cuda_runtime.h>
#include <math.h>
#include <stdint.h>

#define BB 8
#define LL 2048
#define DM 512
#define DI 1024
#define NH 16
#define HD 64
#define CD 1056
#define DIP 2096
#define MT (BB*LL)   // 16384 tokens

// ---------------- scratch (static device globals; no allocation) ----------------
__device__ float g_zx [2ull*MT*DIP];
__device__ float g_xbc[2ull*MT*CD];
__device__ float g_dt [2ull*MT*NH];
__device__ float g_dA [2ull*MT*NH];
__device__ float g_y  [2ull*MT*DI];
__device__ float g_g  [2ull*MT*DI];

__device__ __forceinline__ float siluf(float v)     { return v / (1.f + expf(-v)); }
__device__ __forceinline__ float softplusf(float v) { return fmaxf(v, 0.f) + log1pf(expf(-fabsf(v))); }
__device__ __forceinline__ uint32_t f2tf32(float f) {
    uint32_t r; asm("cvt.rna.tf32.f32 %0, %1;" : "=r"(r) : "f"(f)); return r;
}
__device__ __forceinline__ void mma8(float* c, const uint32_t* a, const uint32_t* b) {
    asm volatile(
        "mma.sync.aligned.m16n8k8.row.col.f32.tf32.tf32.f32 "
        "{%0,%1,%2,%3}, {%4,%5,%6,%7}, {%8,%9}, {%0,%1,%2,%3};"
        : "+f"(c[0]), "+f"(c[1]), "+f"(c[2]), "+f"(c[3])
        : "r"(a[0]), "r"(a[1]), "r"(a[2]), "r"(a[3]), "r"(b[0]), "r"(b[1]));
}

// ============================================================================
// tf32 mma.sync GEMM: C[M,N] = A[M,K] * B[N,K]^T  (fp32 accumulate)
// BM=128, BN=128, BK=16. 256 threads = 8 warps (2 x 4), warp tile 64x32.
// ============================================================================
template<bool ACC>
__global__ void __launch_bounds__(256)
gemm_mma(const float* __restrict__ A, const float* __restrict__ B,
         float* __restrict__ C, int N, int K, int ldc)
{
    __shared__ uint32_t As[2][16][132];
    __shared__ uint32_t Bs[2][16][132];

    const int tid  = threadIdx.x;
    const int lane = tid & 31;
    const int wid  = tid >> 5;
    const int mw   = wid & 1;    // 0..1
    const int nw   = wid >> 1;   // 0..3
    const int m0   = blockIdx.y * 128;
    const int n0   = blockIdx.x * 128;

    const int lr = tid >> 2;          // 0..63 (row)
    const int lc = (tid & 3) << 2;    // 0,4,8,12 (col base)

    float acc[4][4][4];
#pragma unroll
    for (int i = 0; i < 4; i++)
#pragma unroll
        for (int j = 0; j < 4; j++)
#pragma unroll
            for (int r = 0; r < 4; r++) acc[i][j][r] = 0.f;

    const int T = K >> 4;

    auto load_tile = [&](int kt, int buf) {
        const int k0 = kt << 4;
#pragma unroll
        for (int i = 0; i < 2; i++) {
            int row = lr + i * 64;
            float4 va = *(const float4*)(A + (size_t)(m0 + row) * K + k0 + lc);
            As[buf][lc+0][row] = f2tf32(va.x);
            As[buf][lc+1][row] = f2tf32(va.y);
            As[buf][lc+2][row] = f2tf32(va.z);
            As[buf][lc+3][row] = f2tf32(va.w);
            float4 vb = make_float4(0.f, 0.f, 0.f, 0.f);
            if (n0 + row < N)
                vb = *(const float4*)(B + (size_t)(n0 + row) * K + k0 + lc);
            Bs[buf][lc+0][row] = f2tf32(vb.x);
            Bs[buf][lc+1][row] = f2tf32(vb.y);
            Bs[buf][lc+2][row] = f2tf32(vb.z);
            Bs[buf][lc+3][row] = f2tf32(vb.w);
        }
    };

    load_tile(0, 0);
    __syncthreads();

    const int g = lane >> 2;   // 0..7
    const int q = lane & 3;    // 0..3

    for (int kt = 0; kt < T; kt++) {
        const int cur = kt & 1;
        // prefetch next tile into the other buffer (no sync needed: disjoint)
        if (kt + 1 < T) load_tile(kt + 1, cur ^ 1);

#pragma unroll
        for (int kk = 0; kk < 16; kk += 8) {
            uint32_t af[4][4], bf[4][2];
#pragma unroll
            for (int mt = 0; mt < 4; mt++) {
                int row = mw * 64 + mt * 16 + g;
                af[mt][0] = As[cur][kk + q    ][row];
                af[mt][1] = As[cur][kk + q    ][row + 8];
                af[mt][2] = As[cur][kk + q + 4][row];
                af[mt][3] = As[cur][kk + q + 4][row + 8];
            }
#pragma unroll
            for (int nt = 0; nt < 4; nt++) {
                int col = nw * 32 + nt * 8 + g;
                bf[nt][0] = Bs[cur][kk + q    ][col];
                bf[nt][1] = Bs[cur][kk + q + 4][col];
            }
#pragma unroll
            for (int mt = 0; mt < 4; mt++)
#pragma unroll
                for (int nt = 0; nt < 4; nt++)
                    mma8(acc[mt][nt], af[mt], bf[nt]);
        }
        __syncthreads();
    }

    // epilogue: c0,c1 at (row, col..col+1); c2,c3 at (row+8, col..col+1)
#pragma unroll
    for (int mt = 0; mt < 4; mt++) {
        int row = m0 + mw * 64 + mt * 16 + g;
#pragma unroll
        for (int nt = 0; nt < 4; nt++) {
            int n = n0 + nw * 32 + nt * 8 + q * 2;
            if (n < N) {
                float* p0 = C + (size_t)row * ldc + n;
                float* p1 = C + (size_t)(row + 8) * ldc + n;
                float2 v0 = make_float2(acc[mt][nt][0], acc[mt][nt][1]);
                float2 v1 = make_float2(acc[mt][nt][2], acc[mt][nt][3]);
                if (ACC) {
                    float2 o0 = *(const float2*)p0, o1 = *(const float2*)p1;
                    v0.x += o0.x; v0.y += o0.y; v1.x += o1.x; v1.y += o1.y;
                }
                *(float2*)p0 = v0;
                *(float2*)p1 = v1;
            }
        }
    }
}

// ---------------- depthwise causal/anticausal conv(4) + bias + SiLU ----------------
__global__ __launch_bounds__(256)
void conv_silu_k(const float* __restrict__ cwF, const float* __restrict__ cbF,
                 const float* __restrict__ cwB, const float* __restrict__ cbB)
{
    long idx = (long)blockIdx.x * 256 + threadIdx.x;
    const long total = 2L * MT * CD;
    if (idx >= total) return;
    int  c = (int)(idx % CD);
    long r = idx / CD;
    int  t = (int)(r % LL);
    int  d = (int)(r / MT);

    const float* w = (d == 0 ? cwF : cwB) + c * 4;
    float acc = (d == 0 ? cbF : cbB)[c];
    const float* zin = g_zx + r * (long)DIP + DI + c;

    if (d == 0) {
#pragma unroll
        for (int k = 0; k < 4; k++) {
            int tt = t - 3 + k;
            if (tt >= 0) acc = fmaf(w[k], zin[(long)(k - 3) * DIP], acc);
        }
    } else {
#pragma unroll
        for (int k = 0; k < 4; k++) {
            int tt = t + 3 - k;
            if (tt < LL) acc = fmaf(w[k], zin[(long)(3 - k) * DIP], acc);
        }
    }
    g_xbc[idx] = siluf(acc);
}

// ---------------- dt in exact fp32: dt_raw = x[token] . W_dt[h] ----------------
__global__ __launch_bounds__(128)
void dadt_k(const float* __restrict__ x,
            const float* __restrict__ ipwF, const float* __restrict__ ipwB,
            const float* __restrict__ dbF,  const float* __restrict__ alF,
            const float* __restrict__ dbB,  const float* __restrict__ alB)
{
    int r = blockIdx.x;                 // 0 .. 2*MT-1
    int d = r >> 14;                    // MT = 2^14
    int token = r & (MT - 1);
    const float* xr = x + (size_t)token * DM;
    const float* W  = (d ? ipwB : ipwF) + (size_t)(DI + CD) * DM;
    int tid = threadIdx.x;
    int h  = tid >> 3;                  // 16 heads
    int l8 = tid & 7;
    const float* wr = W + (size_t)h * DM;

    float s = 0.f;
#pragma unroll
    for (int j = 0; j < 16; j++) {
        int k = j * 32 + l8 * 4;
        float4 xv = *(const float4*)(xr + k);
        float4 wv = *(const float4*)(wr + k);
        s = fmaf(xv.x, wv.x, s); s = fmaf(xv.y, wv.y, s);
        s = fmaf(xv.z, wv.z, s); s = fmaf(xv.w, wv.w, s);
    }
    s += __shfl_xor_sync(~0u, s, 1);
    s += __shfl_xor_sync(~0u, s, 2);
    s += __shfl_xor_sync(~0u, s, 4);
    if (l8 == 0) {
        float dt = softplusf(s + (d ? dbB : dbF)[h]);
        float A  = -expf((d ? alB : alF)[h]);
        g_dt[(size_t)r * NH + h] = dt;
        g_dA[(size_t)r * NH + h] = expf(dt * A);
    }
}

// ---------------- selective scan: depth-2 software pipeline ----------------
__device__ __forceinline__ float ld_bc(long row, int p, int h)
{
    if (p < 32)  return g_xbc[row * (long)CD + DI + p];
    if (p == 32) return g_dt[row * (long)NH + h];
    return g_dA[row * (long)NH + h];
}

__global__ __launch_bounds__(64)
void scan_k(const float* __restrict__ DpF, const float* __restrict__ DpB)
{
    int bid = blockIdx.x;          // 256 = 2 dirs * 8 batch * 16 heads
    int d   = bid >> 7;
    int rem = bid & 127;
    int b   = rem >> 4;
    int h   = rem & 15;
    int p   = threadIdx.x;

    __shared__ float sBC[2][34];   // B[16], C[16], dt, dA
    float hs[16];
#pragma unroll
    for (int n = 0; n < 16; n++) hs[n] = 0.f;
    float dp = (d == 0 ? DpF : DpB)[h];
    long base0 = (long)d * MT + (long)b * LL;

    auto rowof = [&](int s) -> long {
        int sc = s < LL ? s : LL - 1;
        int t = (d == 0) ? sc : (LL - 1 - sc);
        return base0 + t;
    };

    long r0 = rowof(0), r1 = rowof(1);
    float x0 = g_xbc[r0 * (long)CD + h * HD + p];
    float x1 = g_xbc[r1 * (long)CD + h * HD + p];
    if (p < 34) sBC[0][p] = ld_bc(r0, p, h);
    float b1v = (p < 34) ? ld_bc(r1, p, h) : 0.f;
    __syncthreads();

    int cur = 0;
    for (int s = 0; s < LL; ++s) {
        long r2 = rowof(s + 2);
        float x2  = g_xbc[r2 * (long)CD + h * HD + p];
        float b2v = (p < 34) ? ld_bc(r2, p, h) : 0.f;

        float dtv = sBC[cur][32], dAv = sBC[cur][33];
        float coef = dtv * x0;
        float y = 0.f;
#pragma unroll
        for (int n = 0; n < 16; n++) {
            hs[n] = fmaf(hs[n], dAv, coef * sBC[cur][n]);
            y = fmaf(hs[n], sBC[cur][16 + n], y);
        }
        long row = rowof(s);
        g_y[row * (long)DI + h * HD + p] = fmaf(dp, x0, y);

        if (p < 34) sBC[cur ^ 1][p] = b1v;
        __syncthreads();
        x0 = x1; x1 = x2; b1v = b2v; cur ^= 1;
    }
}

// ---------------- gated RMSNorm ----------------
__global__ __launch_bounds__(256)
void gnorm_k(const float* __restrict__ nwF, const float* __restrict__ nwB)
{
    long r = blockIdx.x;
    int  d = (int)(r / MT);
    const float* nw = (d == 0) ? nwF : nwB;
    const float* yp = g_y  + r * (long)DI;
    const float* zp = g_zx + r * (long)DIP;

    int i0 = threadIdx.x * 4;
    float v[4];
    float ss = 0.f;
#pragma unroll
    for (int j = 0; j < 4; j++) {
        float val = yp[i0 + j] * siluf(zp[i0 + j]);
        v[j] = val;
        ss = fmaf(val, val, ss);
    }
#pragma unroll
    for (int off = 16; off; off >>= 1) ss += __shfl_xor_sync(~0u, ss, off);
    __shared__ float ws[8];
    if ((threadIdx.x & 31) == 0) ws[threadIdx.x >> 5] = ss;
    __syncthreads();
    float tot = ws[0] + ws[1] + ws[2] + ws[3] + ws[4] + ws[5] + ws[6] + ws[7];
    float scale = rsqrtf(tot * (1.f / 1024.f) + 1e-5f);
#pragma unroll
    for (int j = 0; j < 4; j++)
        g_g[r * (long)DI + i0 + j] = v[j] * scale * nw[i0 + j];
}

// ---------------- launch ----------------
extern "C" void kernel_launch(void* const* d_in, const int* in_sizes, int n_in,
                              void* d_out, int out_size)
{
    const float* x    = (const float*)d_in[0];
    const float* ipwF = (const float*)d_in[1];
    const float* cwF  = (const float*)d_in[2];
    const float* cbF  = (const float*)d_in[3];
    const float* dbF  = (const float*)d_in[4];
    const float* alF  = (const float*)d_in[5];
    const float* dpF  = (const float*)d_in[6];
    const float* nwF  = (const float*)d_in[7];
    const float* opF  = (const float*)d_in[8];
    const float* ipwB = (const float*)d_in[9];
    const float* cwB  = (const float*)d_in[10];
    const float* cbB  = (const float*)d_in[11];
    const float* dbB  = (const float*)d_in[12];
    const float* alB  = (const float*)d_in[13];
    const float* dpB  = (const float*)d_in[14];
    const float* nwB  = (const float*)d_in[15];
    const float* opB  = (const float*)d_in[16];
    float* out = (float*)d_out;

    float *zx_d, *g_d;
    cudaGetSymbolAddress((void**)&zx_d, g_zx);
    cudaGetSymbolAddress((void**)&g_d,  g_g);

    // 1) in_proj (tf32 mma.sync tensor cores), both directions
    gemm_mma<false><<<dim3(17, 128), 256>>>(x, ipwF, zx_d,                  DIP, DM, DIP);
    gemm_mma<false><<<dim3(17, 128), 256>>>(x, ipwB, zx_d + (size_t)MT*DIP, DIP, DM, DIP);

    // 2) depthwise conv + silu
    {
        long total = 2L * MT * CD;
        conv_silu_k<<<(unsigned)((total + 255) / 256), 256>>>(cwF, cbF, cwB, cbB);
    }

    // 3) dt / dA (exact fp32 dot products from x)
    dadt_k<<<2 * MT, 128>>>(x, ipwF, ipwB, dbF, alF, dbB, alB);

    // 4) selective scan
    scan_k<<<256, 64>>>(dpF, dpB);

    // 5) gated RMSNorm
    gnorm_k<<<2 * MT, 256>>>(nwF, nwB);

    // 6) out_proj: fwd writes, bwd accumulates
    gemm_mma<false><<<dim3(4, 128), 256>>>(g_d,                  opF, out, DM, DI, DM);
    gemm_mma<true ><<<dim3(4, 128), 256>>>(g_d + (size_t)MT*DI,  opB, out, DM, DI, DM);
}

// round 4
// speedup vs baseline: 2.7610x; 1.5071x over previous
#include <cuda_runtime.h>
#include <math.h>
#include <stdint.h>

#define BB 8
#define LL 2048
#define DM 512
#define DI 1024
#define NH 16
#define HD 64
#define CD 1056
#define DIP 2096
#define MT (BB*LL)      // 16384 tokens
#define CL 128          // scan chunk length
#define NC (LL/CL)      // 16 chunks
#define NSCAN 256       // 2 dirs * 8 batch * 16 heads

// ---------------- scratch (static device globals; no allocation) ----------------
__device__ float g_zx [2ull*MT*DIP];
__device__ float g_xbc[2ull*MT*CD];
__device__ float g_dt [2ull*MT*NH];
__device__ float g_dA [2ull*MT*NH];
__device__ float g_y  [2ull*MT*DI];
__device__ float g_g  [2ull*MT*DI];
__device__ float g_P  [(size_t)NSCAN*LL];            // cumulative decay within chunk
__device__ float g_S  [(size_t)NSCAN*NC*HD*16];      // chunk-final states
__device__ float g_hin[(size_t)NSCAN*NC*HD*16];      // chunk-incoming states

__device__ __forceinline__ float siluf(float v)     { return v / (1.f + expf(-v)); }
__device__ __forceinline__ float softplusf(float v) { return fmaxf(v, 0.f) + log1pf(expf(-fabsf(v))); }
__device__ __forceinline__ uint32_t f2tf32(float f) {
    uint32_t r; asm("cvt.rna.tf32.f32 %0, %1;" : "=r"(r) : "f"(f)); return r;
}
__device__ __forceinline__ void mma8(float* c, const uint32_t* a, const uint32_t* b) {
    asm volatile(
        "mma.sync.aligned.m16n8k8.row.col.f32.tf32.tf32.f32 "
        "{%0,%1,%2,%3}, {%4,%5,%6,%7}, {%8,%9}, {%0,%1,%2,%3};"
        : "+f"(c[0]), "+f"(c[1]), "+f"(c[2]), "+f"(c[3])
        : "r"(a[0]), "r"(a[1]), "r"(a[2]), "r"(a[3]), "r"(b[0]), "r"(b[1]));
}

// ============================================================================
// GEMM core pieces (BM=128, BN=128, BK=16; 8 warps 2x4, warp tile 64x32)
// ============================================================================
#define GEMM_PROLOGUE \
    __shared__ uint32_t As[2][16][132]; \
    __shared__ uint32_t Bs[2][16][132]; \
    const int tid  = threadIdx.x; \
    const int lane = tid & 31; \
    const int wid  = tid >> 5; \
    const int mw   = wid & 1; \
    const int nw   = wid >> 1; \
    const int lr = tid >> 2; \
    const int lc = (tid & 3) << 2; \
    const int g = lane >> 2; \
    const int q = lane & 3; \
    float acc[4][4][4]; \
    _Pragma("unroll") for (int i = 0; i < 4; i++) \
    _Pragma("unroll") for (int j = 0; j < 4; j++) \
    _Pragma("unroll") for (int r = 0; r < 4; r++) acc[i][j][r] = 0.f;

#define GEMM_MAINLOOP(T) \
    load_tile(0, 0); \
    __syncthreads(); \
    for (int kt = 0; kt < (T); kt++) { \
        const int cur = kt & 1; \
        if (kt + 1 < (T)) load_tile(kt + 1, cur ^ 1); \
        _Pragma("unroll") \
        for (int kk = 0; kk < 16; kk += 8) { \
            uint32_t af[4][4], bf[4][2]; \
            _Pragma("unroll") \
            for (int mt = 0; mt < 4; mt++) { \
                int row = mw * 64 + mt * 16 + g; \
                af[mt][0] = As[cur][kk + q    ][row]; \
                af[mt][1] = As[cur][kk + q    ][row + 8]; \
                af[mt][2] = As[cur][kk + q + 4][row]; \
                af[mt][3] = As[cur][kk + q + 4][row + 8]; \
            } \
            _Pragma("unroll") \
            for (int nt = 0; nt < 4; nt++) { \
                int col = nw * 32 + nt * 8 + g; \
                bf[nt][0] = Bs[cur][kk + q    ][col]; \
                bf[nt][1] = Bs[cur][kk + q + 4][col]; \
            } \
            _Pragma("unroll") \
            for (int mt = 0; mt < 4; mt++) \
            _Pragma("unroll") \
            for (int nt = 0; nt < 4; nt++) \
                mma8(acc[mt][nt], af[mt], bf[nt]); \
        } \
        __syncthreads(); \
    }

// ---------------- in_proj: grid (17,128,2); z selects direction ----------------
__global__ void __launch_bounds__(256)
gemm_in(const float* __restrict__ A, const float* __restrict__ B0,
        const float* __restrict__ B1, float* __restrict__ Cb)
{
    const float* B = blockIdx.z ? B1 : B0;
    float* C = Cb + (size_t)blockIdx.z * MT * DIP;
    const int m0 = blockIdx.y * 128, n0 = blockIdx.x * 128;
    const int N = DIP, K = DM;

    GEMM_PROLOGUE

    auto load_tile = [&](int kt, int buf) {
        const int k0 = kt << 4;
#pragma unroll
        for (int i = 0; i < 2; i++) {
            int row = lr + i * 64;
            float4 va = *(const float4*)(A + (size_t)(m0 + row) * K + k0 + lc);
            As[buf][lc+0][row] = f2tf32(va.x);
            As[buf][lc+1][row] = f2tf32(va.y);
            As[buf][lc+2][row] = f2tf32(va.z);
            As[buf][lc+3][row] = f2tf32(va.w);
            float4 vb = make_float4(0.f, 0.f, 0.f, 0.f);
            if (n0 + row < N)
                vb = *(const float4*)(B + (size_t)(n0 + row) * K + k0 + lc);
            Bs[buf][lc+0][row] = f2tf32(vb.x);
            Bs[buf][lc+1][row] = f2tf32(vb.y);
            Bs[buf][lc+2][row] = f2tf32(vb.z);
            Bs[buf][lc+3][row] = f2tf32(vb.w);
        }
    };

    GEMM_MAINLOOP(K >> 4)

#pragma unroll
    for (int mt = 0; mt < 4; mt++) {
        int row = m0 + mw * 64 + mt * 16 + g;
#pragma unroll
        for (int nt = 0; nt < 4; nt++) {
            int n = n0 + nw * 32 + nt * 8 + q * 2;
            if (n < N) {
                *(float2*)(C + (size_t)row * DIP + n) =
                    make_float2(acc[mt][nt][0], acc[mt][nt][1]);
                *(float2*)(C + (size_t)(row + 8) * DIP + n) =
                    make_float2(acc[mt][nt][2], acc[mt][nt][3]);
            }
        }
    }
}

// ---------------- out_proj: K-concat of fwd+bwd (K=2048) -> single write ----------------
__global__ void __launch_bounds__(256)
gemm_out(const float* __restrict__ A0, const float* __restrict__ A1,
         const float* __restrict__ B0, const float* __restrict__ B1,
         float* __restrict__ C)
{
    const int m0 = blockIdx.y * 128, n0 = blockIdx.x * 128;
    const int K = 2 * DI;

    GEMM_PROLOGUE

    auto load_tile = [&](int kt, int buf) {
        const int k0 = kt << 4;
        const float* Ap; const float* Bp; int kl;
        if (k0 < DI) { Ap = A0; Bp = B0; kl = k0; }
        else         { Ap = A1; Bp = B1; kl = k0 - DI; }
#pragma unroll
        for (int i = 0; i < 2; i++) {
            int row = lr + i * 64;
            float4 va = *(const float4*)(Ap + (size_t)(m0 + row) * DI + kl + lc);
            As[buf][lc+0][row] = f2tf32(va.x);
            As[buf][lc+1][row] = f2tf32(va.y);
            As[buf][lc+2][row] = f2tf32(va.z);
            As[buf][lc+3][row] = f2tf32(va.w);
            float4 vb = *(const float4*)(Bp + (size_t)(n0 + row) * DI + kl + lc);
            Bs[buf][lc+0][row] = f2tf32(vb.x);
            Bs[buf][lc+1][row] = f2tf32(vb.y);
            Bs[buf][lc+2][row] = f2tf32(vb.z);
            Bs[buf][lc+3][row] = f2tf32(vb.w);
        }
    };

    GEMM_MAINLOOP(K >> 4)

#pragma unroll
    for (int mt = 0; mt < 4; mt++) {
        int row = m0 + mw * 64 + mt * 16 + g;
#pragma unroll
        for (int nt = 0; nt < 4; nt++) {
            int n = n0 + nw * 32 + nt * 8 + q * 2;
            *(float2*)(C + (size_t)row * DM + n) =
                make_float2(acc[mt][nt][0], acc[mt][nt][1]);
            *(float2*)(C + (size_t)(row + 8) * DM + n) =
                make_float2(acc[mt][nt][2], acc[mt][nt][3]);
        }
    }
}

// ---------------- depthwise causal/anticausal conv(4) + bias + SiLU ----------------
__global__ __launch_bounds__(256)
void conv_silu_k(const float* __restrict__ cwF, const float* __restrict__ cbF,
                 const float* __restrict__ cwB, const float* __restrict__ cbB)
{
    long idx = (long)blockIdx.x * 256 + threadIdx.x;
    const long total = 2L * MT * CD;
    if (idx >= total) return;
    int  c = (int)(idx % CD);
    long r = idx / CD;
    int  t = (int)(r % LL);
    int  d = (int)(r / MT);

    const float* w = (d == 0 ? cwF : cwB) + c * 4;
    float acc = (d == 0 ? cbF : cbB)[c];
    const float* zin = g_zx + r * (long)DIP + DI + c;

    if (d == 0) {
#pragma unroll
        for (int k = 0; k < 4; k++) {
            int tt = t - 3 + k;
            if (tt >= 0) acc = fmaf(w[k], zin[(long)(k - 3) * DIP], acc);
        }
    } else {
#pragma unroll
        for (int k = 0; k < 4; k++) {
            int tt = t + 3 - k;
            if (tt < LL) acc = fmaf(w[k], zin[(long)(3 - k) * DIP], acc);
        }
    }
    g_xbc[idx] = siluf(acc);
}

// ---------------- dt in exact fp32: dt_raw = x[token] . W_dt[h] ----------------
__global__ __launch_bounds__(128)
void dadt_k(const float* __restrict__ x,
            const float* __restrict__ ipwF, const float* __restrict__ ipwB,
            const float* __restrict__ dbF,  const float* __restrict__ alF,
            const float* __restrict__ dbB,  const float* __restrict__ alB)
{
    int r = blockIdx.x;                 // 0 .. 2*MT-1
    int d = r >> 14;                    // MT = 2^14
    int token = r & (MT - 1);
    const float* xr = x + (size_t)token * DM;
    const float* W  = (d ? ipwB : ipwF) + (size_t)(DI + CD) * DM;
    int tid = threadIdx.x;
    int h  = tid >> 3;
    int l8 = tid & 7;
    const float* wr = W + (size_t)h * DM;

    float s = 0.f;
#pragma unroll
    for (int j = 0; j < 16; j++) {
        int k = j * 32 + l8 * 4;
        float4 xv = *(const float4*)(xr + k);
        float4 wv = *(const float4*)(wr + k);
        s = fmaf(xv.x, wv.x, s); s = fmaf(xv.y, wv.y, s);
        s = fmaf(xv.z, wv.z, s); s = fmaf(xv.w, wv.w, s);
    }
    s += __shfl_xor_sync(~0u, s, 1);
    s += __shfl_xor_sync(~0u, s, 2);
    s += __shfl_xor_sync(~0u, s, 4);
    if (l8 == 0) {
        float dt = softplusf(s + (d ? dbB : dbF)[h]);
        float A  = -expf((d ? alB : alF)[h]);
        g_dt[(size_t)r * NH + h] = dt;
        g_dA[(size_t)r * NH + h] = expf(dt * A);
    }
}

// ---------------- scan pass 1: independent chunk scans (zero initial state) ----------------
__device__ __forceinline__ float ld_bc(long row, int p, int h)
{
    if (p < 32)  return g_xbc[row * (long)CD + DI + p];
    if (p == 32) return g_dt[row * (long)NH + h];
    return g_dA[row * (long)NH + h];
}

__global__ __launch_bounds__(64)
void chunk_scan_k(const float* __restrict__ DpF, const float* __restrict__ DpB)
{
    int blk = blockIdx.x;              // sid*NC + c
    int c   = blk & (NC - 1);
    int sid = blk >> 4;                // NC = 16
    int d = sid >> 7, b = (sid >> 4) & 7, h = sid & 15;
    int p = threadIdx.x;

    __shared__ float sBC[2][34];
    float hs[16];
#pragma unroll
    for (int n = 0; n < 16; n++) hs[n] = 0.f;
    float dp = (d == 0 ? DpF : DpB)[h];
    long base0 = (long)d * MT + (long)b * LL;
    int s0 = c * CL;

    auto rowof = [&](int s) -> long {
        int sc = s < LL ? s : LL - 1;
        int t = (d == 0) ? sc : (LL - 1 - sc);
        return base0 + t;
    };

    long r0 = rowof(s0), r1 = rowof(s0 + 1);
    float x0 = g_xbc[r0 * (long)CD + h * HD + p];
    float x1 = g_xbc[r1 * (long)CD + h * HD + p];
    if (p < 34) sBC[0][p] = ld_bc(r0, p, h);
    float b1v = (p < 34) ? ld_bc(r1, p, h) : 0.f;
    __syncthreads();

    float P = 1.f;
    int cur = 0;
    for (int i = 0; i < CL; ++i) {
        int s = s0 + i;
        long r2 = rowof(s + 2);
        float x2  = g_xbc[r2 * (long)CD + h * HD + p];
        float b2v = (p < 34) ? ld_bc(r2, p, h) : 0.f;

        float dtv = sBC[cur][32], dAv = sBC[cur][33];
        float coef = dtv * x0;
        float y = 0.f;
#pragma unroll
        for (int n = 0; n < 16; n++) {
            hs[n] = fmaf(hs[n], dAv, coef * sBC[cur][n]);
            y = fmaf(hs[n], sBC[cur][16 + n], y);
        }
        P *= dAv;
        long row = rowof(s);
        g_y[row * (long)DI + h * HD + p] = fmaf(dp, x0, y);
        if (p == 0) g_P[(size_t)sid * LL + s] = P;

        if (p < 34) sBC[cur ^ 1][p] = b1v;
        __syncthreads();
        x0 = x1; x1 = x2; b1v = b2v; cur ^= 1;
    }

    float* Sp = g_S + (size_t)blk * (HD * 16) + p * 16;
#pragma unroll
    for (int n = 0; n < 16; n++) Sp[n] = hs[n];
}

// ---------------- scan pass 2: serial chunk-state propagation (16 steps) ----------------
__global__ __launch_bounds__(64)
void state_scan_k()
{
    int sid = blockIdx.x;
    int p = threadIdx.x;
    float hs[16];
#pragma unroll
    for (int n = 0; n < 16; n++) hs[n] = 0.f;

    for (int c = 0; c < NC; c++) {
        size_t off = ((size_t)(sid * NC + c)) * (HD * 16) + p * 16;
#pragma unroll
        for (int n = 0; n < 16; n++) g_hin[off + n] = hs[n];
        float Pt = g_P[(size_t)sid * LL + c * CL + CL - 1];
#pragma unroll
        for (int n = 0; n < 16; n++) hs[n] = fmaf(hs[n], Pt, g_S[off + n]);
    }
}

// ---------------- scan pass 3: y[s] += P[s] * (C[s] . h_in)  (chunks 1..NC-1) ----------------
__global__ __launch_bounds__(64)
void fixup_k()
{
    int blk = blockIdx.x;                  // sid*(NC-1) + (c-1)
    int cm  = blk % (NC - 1);
    int sid = blk / (NC - 1);
    int c   = cm + 1;
    int d = sid >> 7, b = (sid >> 4) & 7, h = sid & 15;
    int p = threadIdx.x;
    long base0 = (long)d * MT + (long)b * LL;

    size_t off = ((size_t)(sid * NC + c)) * (HD * 16) + p * 16;
    float hin[16];
#pragma unroll
    for (int n = 0; n < 16; n++) hin[n] = g_hin[off + n];

    __shared__ float sC[4][16];
    __shared__ float sP[4];
    int s0 = c * CL;

    for (int i = 0; i < CL; i += 4) {
        {
            int tsub = p >> 4, n = p & 15;
            int s = s0 + i + tsub;
            int t = (d == 0) ? s : (LL - 1 - s);
            sC[tsub][n] = g_xbc[(base0 + t) * (long)CD + DI + 16 + n];
            if (n == 0) sP[tsub] = g_P[(size_t)sid * LL + s];
        }
        __syncthreads();
        float av[4];
#pragma unroll
        for (int j = 0; j < 4; j++) {
            float y = 0.f;
#pragma unroll
            for (int n = 0; n < 16; n++) y = fmaf(hin[n], sC[j][n], y);
            av[j] = y;
        }
#pragma unroll
        for (int j = 0; j < 4; j++) {
            int s = s0 + i + j;
            int t = (d == 0) ? s : (LL - 1 - s);
            long row = base0 + t;
            g_y[row * (long)DI + h * HD + p] += sP[j] * av[j];
        }
        __syncthreads();
    }
}

// ---------------- gated RMSNorm ----------------
__global__ __launch_bounds__(256)
void gnorm_k(const float* __restrict__ nwF, const float* __restrict__ nwB)
{
    long r = blockIdx.x;
    int  d = (int)(r / MT);
    const float* nw = (d == 0) ? nwF : nwB;
    const float* yp = g_y  + r * (long)DI;
    const float* zp = g_zx + r * (long)DIP;

    int i0 = threadIdx.x * 4;
    float v[4];
    float ss = 0.f;
#pragma unroll
    for (int j = 0; j < 4; j++) {
        float val = yp[i0 + j] * siluf(zp[i0 + j]);
        v[j] = val;
        ss = fmaf(val, val, ss);
    }
#pragma unroll
    for (int off = 16; off; off >>= 1) ss += __shfl_xor_sync(~0u, ss, off);
    __shared__ float ws[8];
    if ((threadIdx.x & 31) == 0) ws[threadIdx.x >> 5] = ss;
    __syncthreads();
    float tot = ws[0] + ws[1] + ws[2] + ws[3] + ws[4] + ws[5] + ws[6] + ws[7];
    float scale = rsqrtf(tot * (1.f / 1024.f) + 1e-5f);
#pragma unroll
    for (int j = 0; j < 4; j++)
        g_g[r * (long)DI + i0 + j] = v[j] * scale * nw[i0 + j];
}

// ---------------- launch ----------------
extern "C" void kernel_launch(void* const* d_in, const int* in_sizes, int n_in,
                              void* d_out, int out_size)
{
    const float* x    = (const float*)d_in[0];
    const float* ipwF = (const float*)d_in[1];
    const float* cwF  = (const float*)d_in[2];
    const float* cbF  = (const float*)d_in[3];
    const float* dbF  = (const float*)d_in[4];
    const float* alF  = (const float*)d_in[5];
    const float* dpF  = (const float*)d_in[6];
    const float* nwF  = (const float*)d_in[7];
    const float* opF  = (const float*)d_in[8];
    const float* ipwB = (const float*)d_in[9];
    const float* cwB  = (const float*)d_in[10];
    const float* cbB  = (const float*)d_in[11];
    const float* dbB  = (const float*)d_in[12];
    const float* alB  = (const float*)d_in[13];
    const float* dpB  = (const float*)d_in[14];
    const float* nwB  = (const float*)d_in[15];
    const float* opB  = (const float*)d_in[16];
    float* out = (float*)d_out;

    float *zx_d, *g_d;
    cudaGetSymbolAddress((void**)&zx_d, g_zx);
    cudaGetSymbolAddress((void**)&g_d,  g_g);

    // 1) in_proj both directions in one launch (grid.z = dir)
    gemm_in<<<dim3(17, 128, 2), 256>>>(x, ipwF, ipwB, zx_d);

    // 2) depthwise conv + silu
    {
        long total = 2L * MT * CD;
        conv_silu_k<<<(unsigned)((total + 255) / 256), 256>>>(cwF, cbF, cwB, cbB);
    }

    // 3) dt / dA (exact fp32)
    dadt_k<<<2 * MT, 128>>>(x, ipwF, ipwB, dbF, alF, dbB, alB);

    // 4) chunked selective scan
    chunk_scan_k<<<NSCAN * NC, 64>>>(dpF, dpB);
    state_scan_k<<<NSCAN, 64>>>();
    fixup_k<<<NSCAN * (NC - 1), 64>>>();

    // 5) gated RMSNorm
    gnorm_k<<<2 * MT, 256>>>(nwF, nwB);

    // 6) out_proj: single GEMM, K-concat fwd+bwd
    gemm_out<<<dim3(4, 128), 256>>>(g_d, g_d + (size_t)MT * DI, opF, opB, out);
}

// round 5
// speedup vs baseline: 3.5229x; 1.2760x over previous
#include <cuda_runtime.h>
#include <math.h>
#include <stdint.h>

#define BB 8
#define LL 2048
#define DM 512
#define DI 1024
#define NH 16
#define HD 64
#define CD 1056
#define DIP 2096
#define MT (BB*LL)      // 16384 tokens
#define CL 128          // scan chunk length
#define NC (LL/CL)      // 16 chunks
#define NSCAN 256       // 2 dirs * 8 batch * 16 heads

// ---------------- scratch (static device globals; no allocation) ----------------
__device__ float g_zx [2ull*MT*DIP];
__device__ float g_xbc[2ull*MT*CD];
__device__ float g_dt [2ull*MT*NH];
__device__ float g_dA [2ull*MT*NH];
__device__ float g_y  [2ull*MT*DI];
__device__ float g_g  [2ull*MT*DI];
__device__ float g_P  [(size_t)NSCAN*LL];
__device__ float g_S  [(size_t)NSCAN*NC*HD*16];
__device__ float g_hin[(size_t)NSCAN*NC*HD*16];

__device__ __forceinline__ float siluf(float v)     { return v / (1.f + expf(-v)); }
__device__ __forceinline__ float softplusf(float v) { return fmaxf(v, 0.f) + log1pf(expf(-fabsf(v))); }
__device__ __forceinline__ uint32_t f2tf32(float f) {
    uint32_t r; asm("cvt.rna.tf32.f32 %0, %1;" : "=r"(r) : "f"(f)); return r;
}
__device__ __forceinline__ void mma8(float* c, const uint32_t* a, const uint32_t* b) {
    asm volatile(
        "mma.sync.aligned.m16n8k8.row.col.f32.tf32.tf32.f32 "
        "{%0,%1,%2,%3}, {%4,%5,%6,%7}, {%8,%9}, {%0,%1,%2,%3};"
        : "+f"(c[0]), "+f"(c[1]), "+f"(c[2]), "+f"(c[3])
        : "r"(a[0]), "r"(a[1]), "r"(a[2]), "r"(a[3]), "r"(b[0]), "r"(b[1]));
}
__device__ __forceinline__ void cpa16(uint32_t s, const void* g) {
    asm volatile("cp.async.ca.shared.global [%0], [%1], 16;" :: "r"(s), "l"(g));
}
__device__ __forceinline__ void cpa16p(uint32_t s, const void* g, bool pred) {
    int sz = pred ? 16 : 0;
    asm volatile("cp.async.ca.shared.global [%0], [%1], 16, %2;" :: "r"(s), "l"(g), "r"(sz));
}
#define CP_COMMIT() asm volatile("cp.async.commit_group;" ::: "memory")
#define CP_WAIT(n)  asm volatile("cp.async.wait_group %0;" :: "n"(n) : "memory")

// ============================================================================
// GEMM (BM=128, BN=128, BK=16; 8 warps 2x4, warp tile 64x32), cp.async 2-ahead.
// smem layout [row][20] floats: stride 20 -> conflict-free fragment reads.
// ============================================================================
#define GEMM_PROLOGUE \
    __shared__ float As[2][128][20]; \
    __shared__ float Bs[2][128][20]; \
    const int tid  = threadIdx.x; \
    const int lane = tid & 31; \
    const int wid  = tid >> 5; \
    const int mw   = wid & 1; \
    const int nw   = wid >> 1; \
    const int lr = tid >> 2; \
    const int lc = (tid & 3) << 2; \
    const int g = lane >> 2; \
    const int q = lane & 3; \
    float acc[4][4][4]; \
    _Pragma("unroll") for (int i = 0; i < 4; i++) \
    _Pragma("unroll") for (int j = 0; j < 4; j++) \
    _Pragma("unroll") for (int r = 0; r < 4; r++) acc[i][j][r] = 0.f;

#define GEMM_COMPUTE(cur) \
    _Pragma("unroll") \
    for (int kk = 0; kk < 16; kk += 8) { \
        uint32_t af[4][4], bf[4][2]; \
        _Pragma("unroll") \
        for (int mt = 0; mt < 4; mt++) { \
            int row = mw * 64 + mt * 16 + g; \
            af[mt][0] = f2tf32(As[cur][row    ][kk + q    ]); \
            af[mt][1] = f2tf32(As[cur][row + 8][kk + q    ]); \
            af[mt][2] = f2tf32(As[cur][row    ][kk + q + 4]); \
            af[mt][3] = f2tf32(As[cur][row + 8][kk + q + 4]); \
        } \
        _Pragma("unroll") \
        for (int nt = 0; nt < 4; nt++) { \
            int col = nw * 32 + nt * 8 + g; \
            bf[nt][0] = f2tf32(Bs[cur][col][kk + q    ]); \
            bf[nt][1] = f2tf32(Bs[cur][col][kk + q + 4]); \
        } \
        _Pragma("unroll") \
        for (int mt = 0; mt < 4; mt++) \
        _Pragma("unroll") \
        for (int nt = 0; nt < 4; nt++) \
            mma8(acc[mt][nt], af[mt], bf[nt]); \
    }

#define GEMM_MAINLOOP(T) \
    load_tile(0, 0); CP_COMMIT(); \
    load_tile(1, 1); CP_COMMIT(); \
    for (int kt = 0; kt < (T); kt++) { \
        const int cur = kt & 1; \
        if (kt + 1 < (T)) { CP_WAIT(1); } else { CP_WAIT(0); } \
        __syncthreads(); \
        GEMM_COMPUTE(cur) \
        __syncthreads(); \
        if (kt + 2 < (T)) { load_tile(kt + 2, cur); CP_COMMIT(); } \
    }

// ---------------- in_proj: grid (17,128,2); z selects direction ----------------
__global__ void __launch_bounds__(256)
gemm_in(const float* __restrict__ A, const float* __restrict__ B0,
        const float* __restrict__ B1, float* __restrict__ Cb)
{
    const float* B = blockIdx.z ? B1 : B0;
    float* C = Cb + (size_t)blockIdx.z * MT * DIP;
    const int m0 = blockIdx.y * 128, n0 = blockIdx.x * 128;
    const int N = DIP, K = DM;

    GEMM_PROLOGUE

    auto load_tile = [&](int kt, int buf) {
        const int k0 = kt << 4;
#pragma unroll
        for (int i = 0; i < 2; i++) {
            int row = lr + i * 64;
            cpa16((uint32_t)__cvta_generic_to_shared(&As[buf][row][lc]),
                  A + (size_t)(m0 + row) * K + k0 + lc);
            cpa16p((uint32_t)__cvta_generic_to_shared(&Bs[buf][row][lc]),
                   B + (size_t)(n0 + row) * K + k0 + lc, (n0 + row) < N);
        }
    };

    GEMM_MAINLOOP(K >> 4)

#pragma unroll
    for (int mt = 0; mt < 4; mt++) {
        int row = m0 + mw * 64 + mt * 16 + g;
#pragma unroll
        for (int nt = 0; nt < 4; nt++) {
            int n = n0 + nw * 32 + nt * 8 + q * 2;
            if (n < N) {
                *(float2*)(C + (size_t)row * DIP + n) =
                    make_float2(acc[mt][nt][0], acc[mt][nt][1]);
                *(float2*)(C + (size_t)(row + 8) * DIP + n) =
                    make_float2(acc[mt][nt][2], acc[mt][nt][3]);
            }
        }
    }
}

// ---------------- out_proj: K-concat of fwd+bwd (K=2048) -> single write ----------------
__global__ void __launch_bounds__(256)
gemm_out(const float* __restrict__ A0, const float* __restrict__ A1,
         const float* __restrict__ B0, const float* __restrict__ B1,
         float* __restrict__ C)
{
    const int m0 = blockIdx.y * 128, n0 = blockIdx.x * 128;
    const int K = 2 * DI;

    GEMM_PROLOGUE

    auto load_tile = [&](int kt, int buf) {
        const int k0 = kt << 4;
        const float* Ap; const float* Bp; int kl;
        if (k0 < DI) { Ap = A0; Bp = B0; kl = k0; }
        else         { Ap = A1; Bp = B1; kl = k0 - DI; }
#pragma unroll
        for (int i = 0; i < 2; i++) {
            int row = lr + i * 64;
            cpa16((uint32_t)__cvta_generic_to_shared(&As[buf][row][lc]),
                  Ap + (size_t)(m0 + row) * DI + kl + lc);
            cpa16((uint32_t)__cvta_generic_to_shared(&Bs[buf][row][lc]),
                  Bp + (size_t)(n0 + row) * DI + kl + lc);
        }
    };

    GEMM_MAINLOOP(K >> 4)

#pragma unroll
    for (int mt = 0; mt < 4; mt++) {
        int row = m0 + mw * 64 + mt * 16 + g;
#pragma unroll
        for (int nt = 0; nt < 4; nt++) {
            int n = n0 + nw * 32 + nt * 8 + q * 2;
            *(float2*)(C + (size_t)row * DM + n) =
                make_float2(acc[mt][nt][0], acc[mt][nt][1]);
            *(float2*)(C + (size_t)(row + 8) * DM + n) =
                make_float2(acc[mt][nt][2], acc[mt][nt][3]);
        }
    }
}

// ---------------- depthwise conv(4) + bias + SiLU, 8 outputs per thread ----------------
#define CTT 8
__global__ __launch_bounds__(256)
void conv_silu_k(const float* __restrict__ cwF, const float* __restrict__ cbF,
                 const float* __restrict__ cwB, const float* __restrict__ cbB)
{
    long idx = (long)blockIdx.x * 256 + threadIdx.x;   // exact grid, no bounds check
    int  c  = (int)(idx % CD);
    long q2 = idx / CD;              // 0 .. 2*8*(LL/CTT)-1
    int  tg = (int)(q2 & (LL / CTT - 1));
    int  bd = (int)(q2 >> 8);        // LL/CTT = 256
    int  b  = bd & 7, d = bd >> 3;
    int  t0 = tg * CTT;

    const float* wv = (d == 0 ? cwF : cwB) + c * 4;
    float w0 = wv[0], w1 = wv[1], w2 = wv[2], w3 = wv[3];
    float bias = (d == 0 ? cbF : cbB)[c];
    long rbase = (long)d * MT + (long)b * LL;
    const float* zin = g_zx + rbase * (long)DIP + DI + c;
    float* outp = g_xbc + (rbase + t0) * (long)CD + c;

    float in[CTT + 3];
    if (d == 0) {
#pragma unroll
        for (int j = 0; j < CTT + 3; j++) {
            int tt = t0 - 3 + j;
            in[j] = (tt >= 0) ? zin[(long)tt * DIP] : 0.f;
        }
#pragma unroll
        for (int i = 0; i < CTT; i++) {
            float a = bias;
            a = fmaf(w0, in[i], a); a = fmaf(w1, in[i+1], a);
            a = fmaf(w2, in[i+2], a); a = fmaf(w3, in[i+3], a);
            outp[(long)i * CD] = siluf(a);
        }
    } else {
#pragma unroll
        for (int j = 0; j < CTT + 3; j++) {
            int tt = t0 + j;
            in[j] = (tt < LL) ? zin[(long)tt * DIP] : 0.f;
        }
#pragma unroll
        for (int i = 0; i < CTT; i++) {
            float a = bias;
            a = fmaf(w3, in[i], a); a = fmaf(w2, in[i+1], a);
            a = fmaf(w1, in[i+2], a); a = fmaf(w0, in[i+3], a);
            outp[(long)i * CD] = siluf(a);
        }
    }
}

// ---------------- dt exact fp32, W cached in smem; 64 tokens per block ----------------
__global__ __launch_bounds__(256)
void dadt_k(const float* __restrict__ x,
            const float* __restrict__ ipwF, const float* __restrict__ ipwB,
            const float* __restrict__ dbF,  const float* __restrict__ alF,
            const float* __restrict__ dbB,  const float* __restrict__ alB)
{
    __shared__ float sW[16][512];
    int blk = blockIdx.x;            // 512 = 2 * (MT/64)
    int d   = blk >> 8;
    int tb  = blk & 255;
    int tid = threadIdx.x;

    const float* W = (d ? ipwB : ipwF) + (size_t)(DI + CD) * DM;
#pragma unroll
    for (int j = 0; j < 8; j++)
        ((float4*)&sW[0][0])[j * 256 + tid] = ((const float4*)W)[j * 256 + tid];
    __syncthreads();

    int h = tid >> 4, l = tid & 15;
    float db = (d ? dbB : dbF)[h];
    float A  = -expf((d ? alB : alF)[h]);

    for (int tk = 0; tk < 64; tk++) {
        int token = tb * 64 + tk;
        const float4* xr = (const float4*)(x + (size_t)token * DM);
        const float4* wr = (const float4*)&sW[h][0];
        float s = 0.f;
#pragma unroll
        for (int j = 0; j < 8; j++) {
            float4 xv = xr[l + 16 * j];
            float4 wv = wr[l + 16 * j];
            s = fmaf(xv.x, wv.x, s); s = fmaf(xv.y, wv.y, s);
            s = fmaf(xv.z, wv.z, s); s = fmaf(xv.w, wv.w, s);
        }
        s += __shfl_xor_sync(~0u, s, 1);
        s += __shfl_xor_sync(~0u, s, 2);
        s += __shfl_xor_sync(~0u, s, 4);
        s += __shfl_xor_sync(~0u, s, 8);
        if (l == 0) {
            float dt = softplusf(s + db);
            size_t r = (size_t)d * MT + token;
            g_dt[r * NH + h] = dt;
            g_dA[r * NH + h] = expf(dt * A);
        }
    }
}

// ---------------- scan pass 1: independent chunk scans ----------------
__device__ __forceinline__ float ld_bc(long row, int p, int h)
{
    if (p < 32)  return g_xbc[row * (long)CD + DI + p];
    if (p == 32) return g_dt[row * (long)NH + h];
    return g_dA[row * (long)NH + h];
}

__global__ __launch_bounds__(64)
void chunk_scan_k(const float* __restrict__ DpF, const float* __restrict__ DpB)
{
    int blk = blockIdx.x;
    int c   = blk & (NC - 1);
    int sid = blk >> 4;
    int d = sid >> 7, b = (sid >> 4) & 7, h = sid & 15;
    int p = threadIdx.x;

    __shared__ float sBC[2][34];
    float hs[16];
#pragma unroll
    for (int n = 0; n < 16; n++) hs[n] = 0.f;
    float dp = (d == 0 ? DpF : DpB)[h];
    long base0 = (long)d * MT + (long)b * LL;
    int s0 = c * CL;

    auto rowof = [&](int s) -> long {
        int sc = s < LL ? s : LL - 1;
        int t = (d == 0) ? sc : (LL - 1 - sc);
        return base0 + t;
    };

    long r0 = rowof(s0), r1 = rowof(s0 + 1);
    float x0 = g_xbc[r0 * (long)CD + h * HD + p];
    float x1 = g_xbc[r1 * (long)CD + h * HD + p];
    if (p < 34) sBC[0][p] = ld_bc(r0, p, h);
    float b1v = (p < 34) ? ld_bc(r1, p, h) : 0.f;
    __syncthreads();

    float P = 1.f;
    int cur = 0;
    for (int i = 0; i < CL; ++i) {
        int s = s0 + i;
        long r2 = rowof(s + 2);
        float x2  = g_xbc[r2 * (long)CD + h * HD + p];
        float b2v = (p < 34) ? ld_bc(r2, p, h) : 0.f;

        float dtv = sBC[cur][32], dAv = sBC[cur][33];
        float coef = dtv * x0;
        float y = 0.f;
#pragma unroll
        for (int n = 0; n < 16; n++) {
            hs[n] = fmaf(hs[n], dAv, coef * sBC[cur][n]);
            y = fmaf(hs[n], sBC[cur][16 + n], y);
        }
        P *= dAv;
        long row = rowof(s);
        g_y[row * (long)DI + h * HD + p] = fmaf(dp, x0, y);
        if (p == 0) g_P[(size_t)sid * LL + s] = P;

        if (p < 34) sBC[cur ^ 1][p] = b1v;
        __syncthreads();
        x0 = x1; x1 = x2; b1v = b2v; cur ^= 1;
    }

    float* Sp = g_S + (size_t)blk * (HD * 16) + p * 16;
#pragma unroll
    for (int n = 0; n < 16; n++) Sp[n] = hs[n];
}

// ---------------- scan pass 2: serial chunk-state propagation ----------------
__global__ __launch_bounds__(64)
void state_scan_k()
{
    int sid = blockIdx.x;
    int p = threadIdx.x;
    float hs[16];
#pragma unroll
    for (int n = 0; n < 16; n++) hs[n] = 0.f;

    for (int c = 0; c < NC; c++) {
        size_t off = ((size_t)(sid * NC + c)) * (HD * 16) + p * 16;
#pragma unroll
        for (int n = 0; n < 16; n++) g_hin[off + n] = hs[n];
        float Pt = g_P[(size_t)sid * LL + c * CL + CL - 1];
#pragma unroll
        for (int n = 0; n < 16; n++) hs[n] = fmaf(hs[n], Pt, g_S[off + n]);
    }
}

// ---------------- scan pass 3: y[s] += P[s] * (C[s] . h_in) ----------------
__global__ __launch_bounds__(64)
void fixup_k()
{
    int blk = blockIdx.x;
    int cm  = blk % (NC - 1);
    int sid = blk / (NC - 1);
    int c   = cm + 1;
    int d = sid >> 7, b = (sid >> 4) & 7, h = sid & 15;
    int p = threadIdx.x;
    long base0 = (long)d * MT + (long)b * LL;

    size_t off = ((size_t)(sid * NC + c)) * (HD * 16) + p * 16;
    float hin[16];
#pragma unroll
    for (int n = 0; n < 16; n++) hin[n] = g_hin[off + n];

    __shared__ float sC[4][16];
    __shared__ float sP[4];
    int s0 = c * CL;

    for (int i = 0; i < CL; i += 4) {
        {
            int tsub = p >> 4, n = p & 15;
            int s = s0 + i + tsub;
            int t = (d == 0) ? s : (LL - 1 - s);
            sC[tsub][n] = g_xbc[(base0 + t) * (long)CD + DI + 16 + n];
            if (n == 0) sP[tsub] = g_P[(size_t)sid * LL + s];
        }
        __syncthreads();
        float av[4];
#pragma unroll
        for (int j = 0; j < 4; j++) {
            float y = 0.f;
#pragma unroll
            for (int n = 0; n < 16; n++) y = fmaf(hin[n], sC[j][n], y);
            av[j] = y;
        }
#pragma unroll
        for (int j = 0; j < 4; j++) {
            int s = s0 + i + j;
            int t = (d == 0) ? s : (LL - 1 - s);
            long row = base0 + t;
            g_y[row * (long)DI + h * HD + p] += sP[j] * av[j];
        }
        __syncthreads();
    }
}

// ---------------- gated RMSNorm ----------------
__global__ __launch_bounds__(256)
void gnorm_k(const float* __restrict__ nwF, const float* __restrict__ nwB)
{
    long r = blockIdx.x;
    int  d = (int)(r / MT);
    const float* nw = (d == 0) ? nwF : nwB;
    const float* yp = g_y  + r * (long)DI;
    const float* zp = g_zx + r * (long)DIP;

    int i0 = threadIdx.x * 4;
    float v[4];
    float ss = 0.f;
#pragma unroll
    for (int j = 0; j < 4; j++) {
        float val = yp[i0 + j] * siluf(zp[i0 + j]);
        v[j] = val;
        ss = fmaf(val, val, ss);
    }
#pragma unroll
    for (int off = 16; off; off >>= 1) ss += __shfl_xor_sync(~0u, ss, off);
    __shared__ float ws[8];
    if ((threadIdx.x & 31) == 0) ws[threadIdx.x >> 5] = ss;
    __syncthreads();
    float tot = ws[0] + ws[1] + ws[2] + ws[3] + ws[4] + ws[5] + ws[6] + ws[7];
    float scale = rsqrtf(tot * (1.f / 1024.f) + 1e-5f);
#pragma unroll
    for (int j = 0; j < 4; j++)
        g_g[r * (long)DI + i0 + j] = v[j] * scale * nw[i0 + j];
}

// ---------------- launch ----------------
extern "C" void kernel_launch(void* const* d_in, const int* in_sizes, int n_in,
                              void* d_out, int out_size)
{
    const float* x    = (const float*)d_in[0];
    const float* ipwF = (const float*)d_in[1];
    const float* cwF  = (const float*)d_in[2];
    const float* cbF  = (const float*)d_in[3];
    const float* dbF  = (const float*)d_in[4];
    const float* alF  = (const float*)d_in[5];
    const float* dpF  = (const float*)d_in[6];
    const float* nwF  = (const float*)d_in[7];
    const float* opF  = (const float*)d_in[8];
    const float* ipwB = (const float*)d_in[9];
    const float* cwB  = (const float*)d_in[10];
    const float* cbB  = (const float*)d_in[11];
    const float* dbB  = (const float*)d_in[12];
    const float* alB  = (const float*)d_in[13];
    const float* dpB  = (const float*)d_in[14];
    const float* nwB  = (const float*)d_in[15];
    const float* opB  = (const float*)d_in[16];
    float* out = (float*)d_out;

    float *zx_d, *g_d;
    cudaGetSymbolAddress((void**)&zx_d, g_zx);
    cudaGetSymbolAddress((void**)&g_d,  g_g);

    // 1) in_proj both directions (grid.z = dir), cp.async pipelined tf32 MMA
    gemm_in<<<dim3(17, 128, 2), 256>>>(x, ipwF, ipwB, zx_d);

    // 2) depthwise conv + silu (8 t per thread)
    {
        long total = 2L * 8 * (LL / CTT) * CD;
        conv_silu_k<<<(unsigned)(total / 256), 256>>>(cwF, cbF, cwB, cbB);
    }

    // 3) dt / dA (exact fp32, W in smem)
    dadt_k<<<512, 256>>>(x, ipwF, ipwB, dbF, alF, dbB, alB);

    // 4) chunked selective scan
    chunk_scan_k<<<NSCAN * NC, 64>>>(dpF, dpB);
    state_scan_k<<<NSCAN, 64>>>();
    fixup_k<<<NSCAN * (NC - 1), 64>>>();

    // 5) gated RMSNorm
    gnorm_k<<<2 * MT, 256>>>(nwF, nwB);

    // 6) out_proj: single GEMM, K-concat fwd+bwd
    gemm_out<<<dim3(4, 128), 256>>>(g_d, g_d + (size_t)MT * DI, opF, opB, out);
}